// round 1
// baseline (speedup 1.0000x reference)
#include <cuda_runtime.h>
#include <math.h>

#define Bsz   8
#define Tlen  2048
#define Cdim  1024
#define Edim  4096
#define Mtot  (Bsz * Tlen)       // 16384 tokens
#define CHUNK 64
#define NCHUNK (Tlen / CHUNK)    // 32

// ---------------- scratch (no cudaMalloc allowed) ----------------
__device__ __align__(16) float g_state[(size_t)Mtot * Cdim]; // y, then state (in place)
__device__ __align__(16) float g_out1 [(size_t)Mtot * Cdim]; // gate * x
__device__ __align__(16) float g_h    [(size_t)Mtot * Cdim]; // rmsnorm2 output
__device__ __align__(16) float g_act  [(size_t)Mtot * Edim]; // relu hidden
__device__ __align__(16) float g_csum [Bsz * NCHUNK * Cdim]; // chunk prefix sums

// ---------------- f32x2 helpers ----------------
typedef unsigned long long u64;

__device__ __forceinline__ u64 dupf(float a) {
    u64 d; unsigned r = __float_as_uint(a);
    asm("mov.b64 %0, {%1, %1};" : "=l"(d) : "r"(r));
    return d;
}
__device__ __forceinline__ void fma2(u64 &d, u64 a, u64 b) {
    asm("fma.rn.f32x2 %0, %1, %2, %0;" : "+l"(d) : "l"(a), "l"(b));
}
__device__ __forceinline__ float lo32(u64 v) { return __uint_as_float((unsigned)(v & 0xffffffffull)); }
__device__ __forceinline__ float hi32(u64 v) { return __uint_as_float((unsigned)(v >> 32)); }

// ---------------- rmsnorm (per token row, C=1024) ----------------
__global__ void __launch_bounds__(256) rmsnorm_kernel(const float* __restrict__ x,
                                                      const float* __restrict__ w,
                                                      float* __restrict__ y)
{
    int row = blockIdx.x;
    const float4* xr = reinterpret_cast<const float4*>(x) + (size_t)row * (Cdim / 4);
    const float4* wr = reinterpret_cast<const float4*>(w);

    float4 v = xr[threadIdx.x];
    float ss = v.x * v.x + v.y * v.y + v.z * v.z + v.w * v.w;
    #pragma unroll
    for (int o = 16; o; o >>= 1) ss += __shfl_xor_sync(0xffffffffu, ss, o);

    __shared__ float ws[8];
    int wid = threadIdx.x >> 5, lid = threadIdx.x & 31;
    if (lid == 0) ws[wid] = ss;
    __syncthreads();
    if (threadIdx.x < 8) {
        float t = ws[threadIdx.x];
        t += __shfl_xor_sync(0xffu, t, 1);
        t += __shfl_xor_sync(0xffu, t, 2);
        t += __shfl_xor_sync(0xffu, t, 4);
        if (threadIdx.x == 0) ws[0] = t;
    }
    __syncthreads();
    float inv = rsqrtf(ws[0] * (1.0f / Cdim) + 1e-6f);

    float4 wv = wr[threadIdx.x];
    float4 o;
    o.x = v.x * inv * wv.x;
    o.y = v.y * inv * wv.y;
    o.z = v.z * inv * wv.z;
    o.w = v.w * inv * wv.w;
    reinterpret_cast<float4*>(y)[(size_t)row * (Cdim / 4) + threadIdx.x] = o;
}

// ---------------- chunked scan over T (per (b,c) channel) ----------------
__global__ void __launch_bounds__(256) scan_partial()
{
    int b = blockIdx.x, ch = blockIdx.y, c = blockIdx.z * 256 + threadIdx.x;
    const float* p = g_state + ((size_t)(b * Tlen + ch * CHUNK)) * Cdim + c;
    float s = 0.f;
    #pragma unroll 8
    for (int t = 0; t < CHUNK; t++) s += p[(size_t)t * Cdim];
    g_csum[(b * NCHUNK + ch) * Cdim + c] = s;
}

__global__ void __launch_bounds__(256) scan_prefix()
{
    int b = blockIdx.x;
    int c = blockIdx.y * 256 + threadIdx.x;
    float run = 0.f;
    #pragma unroll
    for (int ch = 0; ch < NCHUNK; ch++) {
        int idx = (b * NCHUNK + ch) * Cdim + c;
        float v = g_csum[idx];
        g_csum[idx] = run;       // exclusive prefix
        run += v;
    }
}

__global__ void __launch_bounds__(256) scan_final()
{
    int b = blockIdx.x, ch = blockIdx.y, c = blockIdx.z * 256 + threadIdx.x;
    float run = g_csum[(b * NCHUNK + ch) * Cdim + c];
    float* p = g_state + ((size_t)(b * Tlen + ch * CHUNK)) * Cdim + c;
    int tg0 = ch * CHUNK;
    #pragma unroll 8
    for (int t = 0; t < CHUNK; t++) {
        run += p[(size_t)t * Cdim];
        float tg = (float)(tg0 + t);
        float scaler = 0.5f * (tg + 1.f) * (tg + 2.f);   // cumsum(arange(1..T))[t], exact in fp32
        p[(size_t)t * Cdim] = run / scaler;
    }
}

// ---------------- fp32 GEMM, 128x128x16 tiles, f32x2 FMA, fused epilogues ----------------
// EPI 0: C = sigmoid(acc + bias) * aux      (gate * x)
// EPI 1: C = relu(acc + bias)
// EPI 2: C = acc + bias + aux               (+ residual)
#define BM 128
#define BN 128
#define BK 16
#define APAD 4

template<int EPI>
__global__ void __launch_bounds__(256) sgemm_kernel(
    const float* __restrict__ A, const float* __restrict__ Bm,
    const float* __restrict__ bias, const float* __restrict__ aux,
    float* __restrict__ Cm, int M, int N, int K)
{
    __shared__ float As[2][BK][BM + APAD];
    __shared__ float Bs[2][BK][BN];

    int tid = threadIdx.x;
    int bm = blockIdx.y * BM;
    int bn = blockIdx.x * BN;

    // global load mapping
    int arow = tid >> 2;            // 0..63  (two passes -> 128 rows)
    int acol = (tid & 3) << 2;      // 0,4,8,12
    int brow = tid >> 5;            // 0..7   (two passes -> 16 rows)
    int bcol = (tid & 31) << 2;     // 0..124

    const float* Aptr = A + (size_t)(bm + arow) * K + acol;
    const float* Bptr = Bm + (size_t)brow * N + bn + bcol;

    // compute mapping: 16x16 threads, each 8(M) x 8(N)
    int tx = tid & 15, ty = tid >> 4;
    int m0 = ty * 8, n0 = tx * 8;

    u64 acc[8][4];
    #pragma unroll
    for (int i = 0; i < 8; i++)
        #pragma unroll
        for (int j = 0; j < 4; j++) acc[i][j] = 0ull;

    int nTiles = K / BK;
    float4 aReg[2], bReg[2];

    // preload tile 0
    #pragma unroll
    for (int i = 0; i < 2; i++) {
        aReg[i] = *(const float4*)(Aptr + (size_t)(i * 64) * K);
        bReg[i] = *(const float4*)(Bptr + (size_t)(i * 8) * N);
    }
    #pragma unroll
    for (int i = 0; i < 2; i++) {
        As[0][acol + 0][arow + i * 64] = aReg[i].x;
        As[0][acol + 1][arow + i * 64] = aReg[i].y;
        As[0][acol + 2][arow + i * 64] = aReg[i].z;
        As[0][acol + 3][arow + i * 64] = aReg[i].w;
        *(float4*)&Bs[0][brow + i * 8][bcol] = bReg[i];
    }
    __syncthreads();

    for (int kt = 0; kt < nTiles; kt++) {
        int cur = kt & 1;
        if (kt + 1 < nTiles) {
            const float* Ap = Aptr + (size_t)(kt + 1) * BK;
            const float* Bp = Bptr + (size_t)(kt + 1) * BK * N;
            #pragma unroll
            for (int i = 0; i < 2; i++) {
                aReg[i] = *(const float4*)(Ap + (size_t)(i * 64) * K);
                bReg[i] = *(const float4*)(Bp + (size_t)(i * 8) * N);
            }
        }

        #pragma unroll
        for (int k = 0; k < BK; k++) {
            float af[8];
            *(float4*)&af[0] = *(const float4*)&As[cur][k][m0];
            *(float4*)&af[4] = *(const float4*)&As[cur][k][m0 + 4];
            u64 bp[4];
            const u64* bsp = (const u64*)&Bs[cur][k][n0];
            bp[0] = bsp[0]; bp[1] = bsp[1]; bp[2] = bsp[2]; bp[3] = bsp[3];
            u64 ad[8];
            #pragma unroll
            for (int i = 0; i < 8; i++) ad[i] = dupf(af[i]);
            #pragma unroll
            for (int i = 0; i < 8; i++)
                #pragma unroll
                for (int j = 0; j < 4; j++) fma2(acc[i][j], ad[i], bp[j]);
        }

        if (kt + 1 < nTiles) {
            int nxt = cur ^ 1;
            #pragma unroll
            for (int i = 0; i < 2; i++) {
                As[nxt][acol + 0][arow + i * 64] = aReg[i].x;
                As[nxt][acol + 1][arow + i * 64] = aReg[i].y;
                As[nxt][acol + 2][arow + i * 64] = aReg[i].z;
                As[nxt][acol + 3][arow + i * 64] = aReg[i].w;
                *(float4*)&Bs[nxt][brow + i * 8][bcol] = bReg[i];
            }
        }
        __syncthreads();
    }

    // epilogue
    #pragma unroll
    for (int i = 0; i < 8; i++) {
        size_t grow = (size_t)(bm + m0 + i) * N + bn + n0;
        #pragma unroll
        for (int j = 0; j < 4; j++) {
            int gn = bn + n0 + j * 2;
            float r0 = lo32(acc[i][j]) + bias[gn];
            float r1 = hi32(acc[i][j]) + bias[gn + 1];
            if (EPI == 0) {
                float a0 = aux[grow + j * 2], a1 = aux[grow + j * 2 + 1];
                r0 = a0 * (1.f / (1.f + expf(-r0)));
                r1 = a1 * (1.f / (1.f + expf(-r1)));
            } else if (EPI == 1) {
                r0 = fmaxf(r0, 0.f);
                r1 = fmaxf(r1, 0.f);
            } else {
                r0 += aux[grow + j * 2];
                r1 += aux[grow + j * 2 + 1];
            }
            float2 o; o.x = r0; o.y = r1;
            *(float2*)&Cm[grow + j * 2] = o;
        }
    }
}

// ---------------- launch ----------------
extern "C" void kernel_launch(void* const* d_in, const int* in_sizes, int n_in,
                              void* d_out, int out_size)
{
    const float* x   = (const float*)d_in[0];
    const float* n1w = (const float*)d_in[1];
    const float* w1  = (const float*)d_in[2];  // (C, C)   in->out
    const float* b1  = (const float*)d_in[3];
    const float* n2w = (const float*)d_in[4];
    const float* w2a = (const float*)d_in[5];  // (C, 4C)
    const float* b2a = (const float*)d_in[6];
    const float* w2b = (const float*)d_in[7];  // (4C, C)
    const float* b2b = (const float*)d_in[8];
    float* out = (float*)d_out;

    float *state, *out1, *h, *act;
    cudaGetSymbolAddress((void**)&state, g_state);
    cudaGetSymbolAddress((void**)&out1,  g_out1);
    cudaGetSymbolAddress((void**)&h,     g_h);
    cudaGetSymbolAddress((void**)&act,   g_act);

    // 1) y = rmsnorm(x, norm1_w)  -> g_state
    rmsnorm_kernel<<<Mtot, 256>>>(x, n1w, state);

    // 2) state = cumsum_T(y) / triangular-scaler   (in place in g_state)
    scan_partial<<<dim3(Bsz, NCHUNK, Cdim / 256), 256>>>();
    scan_prefix <<<dim3(Bsz, Cdim / 256),         256>>>();
    scan_final  <<<dim3(Bsz, NCHUNK, Cdim / 256), 256>>>();

    // 3) out1 = sigmoid(state @ mlp1_w + mlp1_b) * x
    sgemm_kernel<0><<<dim3(Cdim / BN, Mtot / BM), 256>>>(state, w1, b1, x, out1,
                                                         Mtot, Cdim, Cdim);

    // 4) h = rmsnorm(out1, norm2_w)
    rmsnorm_kernel<<<Mtot, 256>>>(out1, n2w, h);

    // 5) act = relu(h @ mlp2_w1 + mlp2_b1)
    sgemm_kernel<1><<<dim3(Edim / BN, Mtot / BM), 256>>>(h, w2a, b2a, nullptr, act,
                                                         Mtot, Edim, Cdim);

    // 6) out = act @ mlp2_w2 + mlp2_b2 + out1
    sgemm_kernel<2><<<dim3(Cdim / BN, Mtot / BM), 256>>>(act, w2b, b2b, out1, out,
                                                         Mtot, Cdim, Edim);
}

// round 3
// speedup vs baseline: 2.5015x; 2.5015x over previous
#include <cuda_runtime.h>
#include <cuda.h>
#include <cuda_bf16.h>
#include <math.h>
#include <stdint.h>

#define Bsz   8
#define Tlen  2048
#define Cdim  1024
#define Edim  4096
#define Mtot  (Bsz * Tlen)       // 16384 tokens
#define CHUNK 64
#define NCHUNK (Tlen / CHUNK)    // 32

typedef __nv_bfloat16 bf16;

// ---------------- scratch (no cudaMalloc allowed) ----------------
__device__ __align__(16) float g_y   [(size_t)Mtot * Cdim];
__device__ __align__(16) float g_out1[(size_t)Mtot * Cdim];
__device__ __align__(16) float g_csum[Bsz * NCHUNK * Cdim];

__device__ __align__(16) bf16 g_s_hi[(size_t)Mtot * Cdim];
__device__ __align__(16) bf16 g_s_lo[(size_t)Mtot * Cdim];
__device__ __align__(16) bf16 g_h_hi[(size_t)Mtot * Cdim];
__device__ __align__(16) bf16 g_h_lo[(size_t)Mtot * Cdim];
__device__ __align__(16) bf16 g_a_hi[(size_t)Mtot * Edim];
__device__ __align__(16) bf16 g_a_lo[(size_t)Mtot * Edim];

// transposed + split weights: [N, K] K-major
__device__ __align__(16) bf16 g_w1T_hi [Cdim * Cdim];
__device__ __align__(16) bf16 g_w1T_lo [Cdim * Cdim];
__device__ __align__(16) bf16 g_w2aT_hi[(size_t)Edim * Cdim];
__device__ __align__(16) bf16 g_w2aT_lo[(size_t)Edim * Cdim];
__device__ __align__(16) bf16 g_w2bT_hi[(size_t)Cdim * Edim];
__device__ __align__(16) bf16 g_w2bT_lo[(size_t)Cdim * Edim];

// ---------------- helpers ----------------
__device__ __forceinline__ uint32_t smem_u32(const void* p) {
    uint32_t a;
    asm("{ .reg .u64 t; cvta.to.shared.u64 t, %1; cvt.u32.u64 %0, t; }" : "=r"(a) : "l"(p));
    return a;
}
__device__ __forceinline__ void cp16(uint32_t s, const void* g) {
    asm volatile("cp.async.cg.shared.global [%0], [%1], 16;" :: "r"(s), "l"(g) : "memory");
}
#define CP_COMMIT() asm volatile("cp.async.commit_group;" ::: "memory")
#define CP_WAIT(n)  asm volatile("cp.async.wait_group %0;" :: "n"(n) : "memory")

#define LDSM_X4(r, addr) \
    asm volatile("ldmatrix.sync.aligned.m8n8.x4.shared.b16 {%0,%1,%2,%3}, [%4];" \
        : "=r"((r)[0]), "=r"((r)[1]), "=r"((r)[2]), "=r"((r)[3]) : "r"(addr))

#define MMA_BF16(d, a, b0, b1) \
    asm volatile("mma.sync.aligned.m16n8k16.row.col.f32.bf16.bf16.f32 " \
        "{%0,%1,%2,%3}, {%4,%5,%6,%7}, {%8,%9}, {%0,%1,%2,%3};" \
        : "+f"((d)[0]), "+f"((d)[1]), "+f"((d)[2]), "+f"((d)[3]) \
        : "r"((a)[0]), "r"((a)[1]), "r"((a)[2]), "r"((a)[3]), "r"(b0), "r"(b1))

__device__ __forceinline__ void split2(float v, bf16& h, bf16& l) {
    h = __float2bfloat16(v);
    l = __float2bfloat16(v - __bfloat162float(h));
}

// ---------------- rmsnorm ----------------
template<bool SPLIT>
__global__ void __launch_bounds__(256) rmsnorm_kernel(const float* __restrict__ x,
                                                      const float* __restrict__ w,
                                                      float* __restrict__ yF,
                                                      bf16* __restrict__ yHi,
                                                      bf16* __restrict__ yLo)
{
    int row = blockIdx.x;
    const float4* xr = reinterpret_cast<const float4*>(x) + (size_t)row * (Cdim / 4);
    float4 v = xr[threadIdx.x];
    float ss = v.x * v.x + v.y * v.y + v.z * v.z + v.w * v.w;
    #pragma unroll
    for (int o = 16; o; o >>= 1) ss += __shfl_xor_sync(0xffffffffu, ss, o);
    __shared__ float ws[8];
    int wid = threadIdx.x >> 5, lid = threadIdx.x & 31;
    if (lid == 0) ws[wid] = ss;
    __syncthreads();
    if (threadIdx.x < 8) {
        float t = ws[threadIdx.x];
        t += __shfl_xor_sync(0xffu, t, 1);
        t += __shfl_xor_sync(0xffu, t, 2);
        t += __shfl_xor_sync(0xffu, t, 4);
        if (threadIdx.x == 0) ws[0] = t;
    }
    __syncthreads();
    float inv = rsqrtf(ws[0] * (1.0f / Cdim) + 1e-6f);

    float4 wv = reinterpret_cast<const float4*>(w)[threadIdx.x];
    float o0 = v.x * inv * wv.x, o1 = v.y * inv * wv.y, o2 = v.z * inv * wv.z, o3 = v.w * inv * wv.w;
    size_t base = (size_t)row * Cdim + threadIdx.x * 4;
    if (SPLIT) {
        bf16 h0,l0,h1,l1,h2,l2,h3,l3;
        split2(o0,h0,l0); split2(o1,h1,l1); split2(o2,h2,l2); split2(o3,h3,l3);
        __nv_bfloat162 ph0; ph0.x=h0; ph0.y=h1;
        __nv_bfloat162 ph1; ph1.x=h2; ph1.y=h3;
        __nv_bfloat162 pl0; pl0.x=l0; pl0.y=l1;
        __nv_bfloat162 pl1; pl1.x=l2; pl1.y=l3;
        *reinterpret_cast<__nv_bfloat162*>(yHi + base)     = ph0;
        *reinterpret_cast<__nv_bfloat162*>(yHi + base + 2) = ph1;
        *reinterpret_cast<__nv_bfloat162*>(yLo + base)     = pl0;
        *reinterpret_cast<__nv_bfloat162*>(yLo + base + 2) = pl1;
    } else {
        float4 o; o.x=o0; o.y=o1; o.z=o2; o.w=o3;
        *reinterpret_cast<float4*>(yF + base) = o;
    }
}

// ---------------- chunked scan ----------------
__global__ void __launch_bounds__(256) scan_partial()
{
    int b = blockIdx.x, ch = blockIdx.y, c = blockIdx.z * 256 + threadIdx.x;
    const float* p = g_y + ((size_t)(b * Tlen + ch * CHUNK)) * Cdim + c;
    float s = 0.f;
    #pragma unroll 8
    for (int t = 0; t < CHUNK; t++) s += p[(size_t)t * Cdim];
    g_csum[(b * NCHUNK + ch) * Cdim + c] = s;
}

__global__ void __launch_bounds__(256) scan_prefix()
{
    int b = blockIdx.x;
    int c = blockIdx.y * 256 + threadIdx.x;
    float run = 0.f;
    #pragma unroll
    for (int ch = 0; ch < NCHUNK; ch++) {
        int idx = (b * NCHUNK + ch) * Cdim + c;
        float v = g_csum[idx];
        g_csum[idx] = run;
        run += v;
    }
}

__global__ void __launch_bounds__(256) scan_final()
{
    int b = blockIdx.x, ch = blockIdx.y, c = blockIdx.z * 256 + threadIdx.x;
    float run = g_csum[(b * NCHUNK + ch) * Cdim + c];
    const float* p = g_y + ((size_t)(b * Tlen + ch * CHUNK)) * Cdim + c;
    size_t ob = ((size_t)(b * Tlen + ch * CHUNK)) * Cdim + c;
    int tg0 = ch * CHUNK;
    #pragma unroll 8
    for (int t = 0; t < CHUNK; t++) {
        run += p[(size_t)t * Cdim];
        float tg = (float)(tg0 + t);
        float scaler = 0.5f * (tg + 1.f) * (tg + 2.f);
        float v = run / scaler;
        bf16 h, l; split2(v, h, l);
        g_s_hi[ob + (size_t)t * Cdim] = h;
        g_s_lo[ob + (size_t)t * Cdim] = l;
    }
}

// ---------------- weight transpose + split ----------------
__global__ void __launch_bounds__(256) transpose_split(const float* __restrict__ in,
                                                       bf16* __restrict__ hi,
                                                       bf16* __restrict__ lo,
                                                       int K, int N)
{
    __shared__ float t[32][33];
    int k0 = blockIdx.x * 32, n0 = blockIdx.y * 32;
    int x = threadIdx.x & 31, y = threadIdx.x >> 5;
    #pragma unroll
    for (int i = y; i < 32; i += 8)
        t[i][x] = in[(size_t)(k0 + i) * N + n0 + x];
    __syncthreads();
    #pragma unroll
    for (int i = y; i < 32; i += 8) {
        float v = t[x][i];
        bf16 h, l; split2(v, h, l);
        size_t o = (size_t)(n0 + i) * K + k0 + x;
        hi[o] = h; lo[o] = l;
    }
}

// ---------------- bf16x3 HMMA GEMM: 128x128x32 tiles, 4-stage cp.async ----------------
// A: [M,K] row-major bf16 (hi/lo), B: [N,K] row-major bf16 (hi/lo) -> C[M,N]
// EPI 0: outF = sigmoid(acc+bias) * aux
// EPI 1: outHi/outLo = split(relu(acc+bias))
// EPI 2: outF = acc + bias + aux
#define BKt    32
#define STG    4
#define TILEB  16384                // A 8KB + B 8KB per stage
#define SMTOT  (STG * TILEB)

__device__ __forceinline__ void load_tile(const bf16* __restrict__ A,
                                          const bf16* __restrict__ B,
                                          int bm, int bn, int koff, int K,
                                          uint32_t sbase, int stage, int tid)
{
    uint32_t sA = sbase + stage * TILEB;
    uint32_t sB = sA + 8192;
    #pragma unroll
    for (int i = 0; i < 2; i++) {
        int idx = tid + i * 256;          // 0..511
        int row = idx >> 2, ch = idx & 3;
        int chs = ch ^ ((row >> 1) & 3);  // swizzle
        uint32_t so = (uint32_t)(row * 64 + chs * 16);
        cp16(sA + so, A + (size_t)(bm + row) * K + koff + ch * 8);
        cp16(sB + so, B + (size_t)(bn + row) * K + koff + ch * 8);
    }
}

template<int EPI>
__global__ void __launch_bounds__(256) mma_gemm(
    const bf16* __restrict__ Ahi, const bf16* __restrict__ Alo,
    const bf16* __restrict__ Bhi, const bf16* __restrict__ Blo,
    const float* __restrict__ bias, const float* __restrict__ aux,
    float* __restrict__ outF, bf16* __restrict__ outHi, bf16* __restrict__ outLo,
    int N, int K)
{
    extern __shared__ __align__(16) char smem[];
    uint32_t sbase = smem_u32(smem);
    int tid = threadIdx.x, wid = tid >> 5, lane = tid & 31;
    int bm = blockIdx.y * 128, bn = blockIdx.x * 128;
    int wm = (wid >> 2) * 64, wn = (wid & 3) * 32;

    int kseg = K / BKt;
    int nkt  = 3 * kseg;

    float acc[4][4][4] = {};

    // prologue: prefetch 3 tiles
    #pragma unroll
    for (int kk = 0; kk < 3; kk++) {
        int seg = kk / kseg, kl = (kk % kseg) * BKt;
        const bf16* As = (seg < 2) ? Ahi : Alo;
        const bf16* Bs = (seg == 1) ? Blo : Bhi;
        load_tile(As, Bs, bm, bn, kl, K, sbase, kk, tid);
        CP_COMMIT();
    }

    // ldmatrix lane constants
    int l8 = lane & 7;
    int aRow  = wm + l8 + ((lane >> 3) & 1) * 8;   // + mf*16
    int aCHi  = (lane >> 4) & 1;                   // chunk bit0
    int aXor  = (aRow >> 1) & 3;
    int bRow  = wn + l8 + ((lane >> 4) & 1) * 8;   // + g*16
    int bCHi  = (lane >> 3) & 1;
    int bXor  = (bRow >> 1) & 3;

    for (int kk = 0; kk < nkt; kk++) {
        if (kk + 3 < nkt) { CP_WAIT(2); } else { CP_WAIT(0); }
        __syncthreads();

        uint32_t sA = sbase + (kk & 3) * TILEB;
        uint32_t sB = sA + 8192;

        #pragma unroll
        for (int ks = 0; ks < 2; ks++) {
            uint32_t a[4][4];
            #pragma unroll
            for (int mf = 0; mf < 4; mf++) {
                uint32_t addr = sA + (uint32_t)((aRow + mf * 16) * 64
                              + (((ks * 2 + aCHi) ^ aXor) * 16));
                LDSM_X4(a[mf], addr);
            }
            uint32_t b[4][2];
            #pragma unroll
            for (int g = 0; g < 2; g++) {
                uint32_t r[4];
                uint32_t addr = sB + (uint32_t)((bRow + g * 16) * 64
                              + (((ks * 2 + bCHi) ^ bXor) * 16));
                LDSM_X4(r, addr);
                b[2*g][0] = r[0]; b[2*g][1] = r[1];
                b[2*g+1][0] = r[2]; b[2*g+1][1] = r[3];
            }
            #pragma unroll
            for (int mf = 0; mf < 4; mf++)
                #pragma unroll
                for (int nf = 0; nf < 4; nf++)
                    MMA_BF16(acc[mf][nf], a[mf], b[nf][0], b[nf][1]);
        }

        if (kk + 3 < nkt) {
            int nt = kk + 3;
            int seg = nt / kseg, kl = (nt % kseg) * BKt;
            const bf16* As = (seg < 2) ? Ahi : Alo;
            const bf16* Bs = (seg == 1) ? Blo : Bhi;
            load_tile(As, Bs, bm, bn, kl, K, sbase, nt & 3, tid);
            CP_COMMIT();
        }
    }

    // epilogue
    int mrow = bm + wm + (lane >> 2);
    int ncol = bn + wn + (lane & 3) * 2;
    #pragma unroll
    for (int mf = 0; mf < 4; mf++) {
        int r0 = mrow + mf * 16;
        #pragma unroll
        for (int nf = 0; nf < 4; nf++) {
            int n = ncol + nf * 8;
            float bz0 = bias[n], bz1 = bias[n + 1];
            float v0 = acc[mf][nf][0] + bz0;
            float v1 = acc[mf][nf][1] + bz1;
            float v2 = acc[mf][nf][2] + bz0;
            float v3 = acc[mf][nf][3] + bz1;
            size_t p0 = (size_t)r0 * N + n;
            size_t p1 = (size_t)(r0 + 8) * N + n;
            if (EPI == 0) {
                float2 a0 = *reinterpret_cast<const float2*>(aux + p0);
                float2 a1 = *reinterpret_cast<const float2*>(aux + p1);
                v0 = a0.x * (1.f / (1.f + expf(-v0)));
                v1 = a0.y * (1.f / (1.f + expf(-v1)));
                v2 = a1.x * (1.f / (1.f + expf(-v2)));
                v3 = a1.y * (1.f / (1.f + expf(-v3)));
                float2 o0; o0.x = v0; o0.y = v1;
                float2 o1; o1.x = v2; o1.y = v3;
                *reinterpret_cast<float2*>(outF + p0) = o0;
                *reinterpret_cast<float2*>(outF + p1) = o1;
            } else if (EPI == 1) {
                v0 = fmaxf(v0, 0.f); v1 = fmaxf(v1, 0.f);
                v2 = fmaxf(v2, 0.f); v3 = fmaxf(v3, 0.f);
                bf16 h0,l0,h1,l1,h2,l2,h3,l3;
                split2(v0,h0,l0); split2(v1,h1,l1);
                split2(v2,h2,l2); split2(v3,h3,l3);
                __nv_bfloat162 ph0; ph0.x=h0; ph0.y=h1;
                __nv_bfloat162 ph1; ph1.x=h2; ph1.y=h3;
                __nv_bfloat162 pl0; pl0.x=l0; pl0.y=l1;
                __nv_bfloat162 pl1; pl1.x=l2; pl1.y=l3;
                *reinterpret_cast<__nv_bfloat162*>(outHi + p0) = ph0;
                *reinterpret_cast<__nv_bfloat162*>(outHi + p1) = ph1;
                *reinterpret_cast<__nv_bfloat162*>(outLo + p0) = pl0;
                *reinterpret_cast<__nv_bfloat162*>(outLo + p1) = pl1;
            } else {
                float2 a0 = *reinterpret_cast<const float2*>(aux + p0);
                float2 a1 = *reinterpret_cast<const float2*>(aux + p1);
                float2 o0; o0.x = v0 + a0.x; o0.y = v1 + a0.y;
                float2 o1; o1.x = v2 + a1.x; o1.y = v3 + a1.y;
                *reinterpret_cast<float2*>(outF + p0) = o0;
                *reinterpret_cast<float2*>(outF + p1) = o1;
            }
        }
    }
}

// ---------------- host ----------------
extern "C" void kernel_launch(void* const* d_in, const int* in_sizes, int n_in,
                              void* d_out, int out_size)
{
    const float* x   = (const float*)d_in[0];
    const float* n1w = (const float*)d_in[1];
    const float* w1  = (const float*)d_in[2];
    const float* b1  = (const float*)d_in[3];
    const float* n2w = (const float*)d_in[4];
    const float* w2a = (const float*)d_in[5];
    const float* b2a = (const float*)d_in[6];
    const float* w2b = (const float*)d_in[7];
    const float* b2b = (const float*)d_in[8];
    float* out = (float*)d_out;

    void *p_shi, *p_slo, *p_hhi, *p_hlo, *p_ahi, *p_alo;
    void *p_w1h, *p_w1l, *p_w2ah, *p_w2al, *p_w2bh, *p_w2bl;
    float *out1, *yf;
    cudaGetSymbolAddress(&p_shi, g_s_hi);   cudaGetSymbolAddress(&p_slo, g_s_lo);
    cudaGetSymbolAddress(&p_hhi, g_h_hi);   cudaGetSymbolAddress(&p_hlo, g_h_lo);
    cudaGetSymbolAddress(&p_ahi, g_a_hi);   cudaGetSymbolAddress(&p_alo, g_a_lo);
    cudaGetSymbolAddress(&p_w1h, g_w1T_hi); cudaGetSymbolAddress(&p_w1l, g_w1T_lo);
    cudaGetSymbolAddress(&p_w2ah, g_w2aT_hi); cudaGetSymbolAddress(&p_w2al, g_w2aT_lo);
    cudaGetSymbolAddress(&p_w2bh, g_w2bT_hi); cudaGetSymbolAddress(&p_w2bl, g_w2bT_lo);
    cudaGetSymbolAddress((void**)&out1, g_out1);
    cudaGetSymbolAddress((void**)&yf, g_y);

    cudaFuncSetAttribute(mma_gemm<0>, cudaFuncAttributeMaxDynamicSharedMemorySize, SMTOT);
    cudaFuncSetAttribute(mma_gemm<1>, cudaFuncAttributeMaxDynamicSharedMemorySize, SMTOT);
    cudaFuncSetAttribute(mma_gemm<2>, cudaFuncAttributeMaxDynamicSharedMemorySize, SMTOT);

    // 1) y = rmsnorm(x)
    rmsnorm_kernel<false><<<Mtot, 256>>>(x, n1w, yf, nullptr, nullptr);

    // 2) state = cumsum(y)/scaler -> split bf16
    scan_partial<<<dim3(Bsz, NCHUNK, Cdim / 256), 256>>>();
    scan_prefix <<<dim3(Bsz, Cdim / 256),         256>>>();
    scan_final  <<<dim3(Bsz, NCHUNK, Cdim / 256), 256>>>();

    // 3) weight transpose + split (concurrent with scan on same stream, ordered anyway)
    transpose_split<<<dim3(Cdim / 32, Cdim / 32), 256>>>(w1,  (bf16*)p_w1h,  (bf16*)p_w1l,  Cdim, Cdim);
    transpose_split<<<dim3(Cdim / 32, Edim / 32), 256>>>(w2a, (bf16*)p_w2ah, (bf16*)p_w2al, Cdim, Edim);
    transpose_split<<<dim3(Edim / 32, Cdim / 32), 256>>>(w2b, (bf16*)p_w2bh, (bf16*)p_w2bl, Edim, Cdim);

    // 4) out1 = sigmoid(state @ w1 + b1) * x
    mma_gemm<0><<<dim3(Cdim / 128, Mtot / 128), 256, SMTOT>>>(
        (bf16*)p_shi, (bf16*)p_slo, (bf16*)p_w1h, (bf16*)p_w1l,
        b1, x, out1, nullptr, nullptr, Cdim, Cdim);

    // 5) h = rmsnorm(out1) -> split
    rmsnorm_kernel<true><<<Mtot, 256>>>(out1, n2w, nullptr, (bf16*)p_hhi, (bf16*)p_hlo);

    // 6) act = relu(h @ w2a + b2a) -> split
    mma_gemm<1><<<dim3(Edim / 128, Mtot / 128), 256, SMTOT>>>(
        (bf16*)p_hhi, (bf16*)p_hlo, (bf16*)p_w2ah, (bf16*)p_w2al,
        b2a, nullptr, nullptr, (bf16*)p_ahi, (bf16*)p_alo, Edim, Cdim);

    // 7) out = act @ w2b + b2b + out1
    mma_gemm<2><<<dim3(Cdim / 128, Mtot / 128), 256, SMTOT>>>(
        (bf16*)p_ahi, (bf16*)p_alo, (bf16*)p_w2bh, (bf16*)p_w2bl,
        b2b, out1, out, nullptr, nullptr, Cdim, Edim);
}

// round 4
// speedup vs baseline: 7.0873x; 2.8332x over previous
#include <cuda_runtime.h>
#include <cuda.h>
#include <cuda_fp16.h>
#include <math.h>
#include <stdint.h>

#define Bsz   8
#define Tlen  2048
#define Cdim  1024
#define Edim  4096
#define Mtot  (Bsz * Tlen)       // 16384 tokens
#define CHUNK 64
#define NCHUNK (Tlen / CHUNK)    // 32

typedef __half f16;

// ---------------- scratch (no cudaMalloc allowed) ----------------
__device__ __align__(16) float g_y   [(size_t)Mtot * Cdim];
__device__ __align__(16) float g_out1[(size_t)Mtot * Cdim];
__device__ __align__(16) float g_csum[Bsz * NCHUNK * Cdim];

__device__ __align__(16) f16 g_s  [(size_t)Mtot * Cdim];   // state (fp16)
__device__ __align__(16) f16 g_h  [(size_t)Mtot * Cdim];   // rmsnorm2 out (fp16)
__device__ __align__(16) f16 g_act[(size_t)Mtot * Edim];   // relu hidden (fp16)

// transposed weights: [N, K] K-major fp16
__device__ __align__(16) f16 g_w1T [Cdim * Cdim];
__device__ __align__(16) f16 g_w2aT[(size_t)Edim * Cdim];
__device__ __align__(16) f16 g_w2bT[(size_t)Cdim * Edim];

// ---------------- helpers ----------------
__device__ __forceinline__ uint32_t smem_u32(const void* p) {
    uint32_t a;
    asm("{ .reg .u64 t; cvta.to.shared.u64 t, %1; cvt.u32.u64 %0, t; }" : "=r"(a) : "l"(p));
    return a;
}
__device__ __forceinline__ void cp16(uint32_t s, const void* g) {
    asm volatile("cp.async.cg.shared.global [%0], [%1], 16;" :: "r"(s), "l"(g) : "memory");
}
#define CP_COMMIT() asm volatile("cp.async.commit_group;" ::: "memory")
#define CP_WAIT(n)  asm volatile("cp.async.wait_group %0;" :: "n"(n) : "memory")

#define LDSM_X4(r, addr) \
    asm volatile("ldmatrix.sync.aligned.m8n8.x4.shared.b16 {%0,%1,%2,%3}, [%4];" \
        : "=r"((r)[0]), "=r"((r)[1]), "=r"((r)[2]), "=r"((r)[3]) : "r"(addr))

#define MMA_F16(d, a, b0, b1) \
    asm volatile("mma.sync.aligned.m16n8k16.row.col.f32.f16.f16.f32 " \
        "{%0,%1,%2,%3}, {%4,%5,%6,%7}, {%8,%9}, {%0,%1,%2,%3};" \
        : "+f"((d)[0]), "+f"((d)[1]), "+f"((d)[2]), "+f"((d)[3]) \
        : "r"((a)[0]), "r"((a)[1]), "r"((a)[2]), "r"((a)[3]), "r"(b0), "r"(b1))

// ---------------- rmsnorm ----------------
template<bool TOF16>
__global__ void __launch_bounds__(256) rmsnorm_kernel(const float* __restrict__ x,
                                                      const float* __restrict__ w,
                                                      float* __restrict__ yF,
                                                      f16* __restrict__ yH)
{
    int row = blockIdx.x;
    const float4* xr = reinterpret_cast<const float4*>(x) + (size_t)row * (Cdim / 4);
    float4 v = xr[threadIdx.x];
    float ss = v.x * v.x + v.y * v.y + v.z * v.z + v.w * v.w;
    #pragma unroll
    for (int o = 16; o; o >>= 1) ss += __shfl_xor_sync(0xffffffffu, ss, o);
    __shared__ float ws[8];
    int wid = threadIdx.x >> 5, lid = threadIdx.x & 31;
    if (lid == 0) ws[wid] = ss;
    __syncthreads();
    if (threadIdx.x < 8) {
        float t = ws[threadIdx.x];
        t += __shfl_xor_sync(0xffu, t, 1);
        t += __shfl_xor_sync(0xffu, t, 2);
        t += __shfl_xor_sync(0xffu, t, 4);
        if (threadIdx.x == 0) ws[0] = t;
    }
    __syncthreads();
    float inv = rsqrtf(ws[0] * (1.0f / Cdim) + 1e-6f);

    float4 wv = reinterpret_cast<const float4*>(w)[threadIdx.x];
    float o0 = v.x * inv * wv.x, o1 = v.y * inv * wv.y, o2 = v.z * inv * wv.z, o3 = v.w * inv * wv.w;
    size_t base = (size_t)row * Cdim + threadIdx.x * 4;
    if (TOF16) {
        __half2 p0; p0.x = __float2half(o0); p0.y = __float2half(o1);
        __half2 p1; p1.x = __float2half(o2); p1.y = __float2half(o3);
        *reinterpret_cast<__half2*>(yH + base)     = p0;
        *reinterpret_cast<__half2*>(yH + base + 2) = p1;
    } else {
        float4 o; o.x = o0; o.y = o1; o.z = o2; o.w = o3;
        *reinterpret_cast<float4*>(yF + base) = o;
    }
}

// ---------------- chunked scan ----------------
__global__ void __launch_bounds__(256) scan_partial()
{
    int b = blockIdx.x, ch = blockIdx.y, c = blockIdx.z * 256 + threadIdx.x;
    const float* p = g_y + ((size_t)(b * Tlen + ch * CHUNK)) * Cdim + c;
    float s = 0.f;
    #pragma unroll 8
    for (int t = 0; t < CHUNK; t++) s += p[(size_t)t * Cdim];
    g_csum[(b * NCHUNK + ch) * Cdim + c] = s;
}

__global__ void __launch_bounds__(256) scan_prefix()
{
    int b = blockIdx.x;
    int c = blockIdx.y * 256 + threadIdx.x;
    float run = 0.f;
    #pragma unroll
    for (int ch = 0; ch < NCHUNK; ch++) {
        int idx = (b * NCHUNK + ch) * Cdim + c;
        float v = g_csum[idx];
        g_csum[idx] = run;
        run += v;
    }
}

__global__ void __launch_bounds__(256) scan_final()
{
    int b = blockIdx.x, ch = blockIdx.y, c = blockIdx.z * 256 + threadIdx.x;
    float run = g_csum[(b * NCHUNK + ch) * Cdim + c];
    const float* p = g_y + ((size_t)(b * Tlen + ch * CHUNK)) * Cdim + c;
    size_t ob = ((size_t)(b * Tlen + ch * CHUNK)) * Cdim + c;
    int tg0 = ch * CHUNK;
    #pragma unroll 8
    for (int t = 0; t < CHUNK; t++) {
        run += p[(size_t)t * Cdim];
        float tg = (float)(tg0 + t);
        float scaler = 0.5f * (tg + 1.f) * (tg + 2.f);
        g_s[ob + (size_t)t * Cdim] = __float2half(run / scaler);
    }
}

// ---------------- weight transpose: in [K,N] fp32 -> out [N,K] fp16 ----------------
__global__ void __launch_bounds__(256) transpose_h(const float* __restrict__ in,
                                                   f16* __restrict__ o16,
                                                   int K, int N)
{
    __shared__ float t[32][33];
    int k0 = blockIdx.x * 32, n0 = blockIdx.y * 32;
    int x = threadIdx.x & 31, y = threadIdx.x >> 5;
    #pragma unroll
    for (int i = y; i < 32; i += 8)
        t[i][x] = in[(size_t)(k0 + i) * N + n0 + x];
    __syncthreads();
    #pragma unroll
    for (int i = y; i < 32; i += 8)
        o16[(size_t)(n0 + i) * K + k0 + x] = __float2half(t[x][i]);
}

// ---------------- fp16 HMMA GEMM: 128x128x32 tiles, 4-stage cp.async ----------------
// A: [M,K] row-major f16, B: [N,K] row-major f16 -> C[M,N]
// EPI 0: outF = sigmoid(acc+bias) * aux
// EPI 1: outH = (f16) relu(acc+bias)
// EPI 2: outF = acc + bias + aux
#define BKt    32
#define STG    4
#define TILEB  16384                // A 8KB + B 8KB per stage
#define SMTOT  (STG * TILEB)

__device__ __forceinline__ void load_tile(const f16* __restrict__ A,
                                          const f16* __restrict__ B,
                                          int bm, int bn, int koff, int K,
                                          uint32_t sbase, int stage, int tid)
{
    uint32_t sA = sbase + stage * TILEB;
    uint32_t sB = sA + 8192;
    #pragma unroll
    for (int i = 0; i < 2; i++) {
        int idx = tid + i * 256;          // 0..511
        int row = idx >> 2, ch = idx & 3;
        int chs = ch ^ ((row >> 1) & 3);  // swizzle
        uint32_t so = (uint32_t)(row * 64 + chs * 16);
        cp16(sA + so, A + (size_t)(bm + row) * K + koff + ch * 8);
        cp16(sB + so, B + (size_t)(bn + row) * K + koff + ch * 8);
    }
}

template<int EPI>
__global__ void __launch_bounds__(256, 2) mma_gemm(
    const f16* __restrict__ Ag, const f16* __restrict__ Bg,
    const float* __restrict__ bias, const float* __restrict__ aux,
    float* __restrict__ outF, f16* __restrict__ outH,
    int N, int K)
{
    extern __shared__ __align__(16) char smem[];
    uint32_t sbase = smem_u32(smem);
    int tid = threadIdx.x, wid = tid >> 5, lane = tid & 31;
    int bm = blockIdx.y * 128, bn = blockIdx.x * 128;
    int wm = (wid >> 2) * 64, wn = (wid & 3) * 32;

    int nkt = K / BKt;

    float acc[4][4][4] = {};

    // prologue: prefetch 3 tiles
    #pragma unroll
    for (int kk = 0; kk < 3; kk++) {
        load_tile(Ag, Bg, bm, bn, kk * BKt, K, sbase, kk, tid);
        CP_COMMIT();
    }

    // ldmatrix lane constants
    int l8 = lane & 7;
    int aRow  = wm + l8 + ((lane >> 3) & 1) * 8;   // + mf*16
    int aCHi  = (lane >> 4) & 1;
    int aXor  = (aRow >> 1) & 3;
    int bRow  = wn + l8 + ((lane >> 4) & 1) * 8;   // + g*16
    int bCHi  = (lane >> 3) & 1;
    int bXor  = (bRow >> 1) & 3;

    for (int kk = 0; kk < nkt; kk++) {
        if (kk + 3 < nkt) { CP_WAIT(2); } else { CP_WAIT(0); }
        __syncthreads();

        uint32_t sA = sbase + (kk & 3) * TILEB;
        uint32_t sB = sA + 8192;

        #pragma unroll
        for (int ks = 0; ks < 2; ks++) {
            uint32_t a[4][4];
            #pragma unroll
            for (int mf = 0; mf < 4; mf++) {
                uint32_t addr = sA + (uint32_t)((aRow + mf * 16) * 64
                              + (((ks * 2 + aCHi) ^ aXor) * 16));
                LDSM_X4(a[mf], addr);
            }
            uint32_t b[4][2];
            #pragma unroll
            for (int g = 0; g < 2; g++) {
                uint32_t r[4];
                uint32_t addr = sB + (uint32_t)((bRow + g * 16) * 64
                              + (((ks * 2 + bCHi) ^ bXor) * 16));
                LDSM_X4(r, addr);
                b[2*g][0] = r[0]; b[2*g][1] = r[1];
                b[2*g+1][0] = r[2]; b[2*g+1][1] = r[3];
            }
            #pragma unroll
            for (int mf = 0; mf < 4; mf++)
                #pragma unroll
                for (int nf = 0; nf < 4; nf++)
                    MMA_F16(acc[mf][nf], a[mf], b[nf][0], b[nf][1]);
        }

        if (kk + 3 < nkt) {
            load_tile(Ag, Bg, bm, bn, (kk + 3) * BKt, K, sbase, (kk + 3) & 3, tid);
            CP_COMMIT();
        }
    }

    // epilogue
    int mrow = bm + wm + (lane >> 2);
    int ncol = bn + wn + (lane & 3) * 2;
    #pragma unroll
    for (int mf = 0; mf < 4; mf++) {
        int r0 = mrow + mf * 16;
        #pragma unroll
        for (int nf = 0; nf < 4; nf++) {
            int n = ncol + nf * 8;
            float bz0 = bias[n], bz1 = bias[n + 1];
            float v0 = acc[mf][nf][0] + bz0;
            float v1 = acc[mf][nf][1] + bz1;
            float v2 = acc[mf][nf][2] + bz0;
            float v3 = acc[mf][nf][3] + bz1;
            size_t p0 = (size_t)r0 * N + n;
            size_t p1 = (size_t)(r0 + 8) * N + n;
            if (EPI == 0) {
                float2 a0 = *reinterpret_cast<const float2*>(aux + p0);
                float2 a1 = *reinterpret_cast<const float2*>(aux + p1);
                v0 = a0.x * (1.f / (1.f + expf(-v0)));
                v1 = a0.y * (1.f / (1.f + expf(-v1)));
                v2 = a1.x * (1.f / (1.f + expf(-v2)));
                v3 = a1.y * (1.f / (1.f + expf(-v3)));
                float2 o0; o0.x = v0; o0.y = v1;
                float2 o1; o1.x = v2; o1.y = v3;
                *reinterpret_cast<float2*>(outF + p0) = o0;
                *reinterpret_cast<float2*>(outF + p1) = o1;
            } else if (EPI == 1) {
                __half2 h0, h1;
                h0.x = __float2half(fmaxf(v0, 0.f));
                h0.y = __float2half(fmaxf(v1, 0.f));
                h1.x = __float2half(fmaxf(v2, 0.f));
                h1.y = __float2half(fmaxf(v3, 0.f));
                *reinterpret_cast<__half2*>(outH + p0) = h0;
                *reinterpret_cast<__half2*>(outH + p1) = h1;
            } else {
                float2 a0 = *reinterpret_cast<const float2*>(aux + p0);
                float2 a1 = *reinterpret_cast<const float2*>(aux + p1);
                float2 o0; o0.x = v0 + a0.x; o0.y = v1 + a0.y;
                float2 o1; o1.x = v2 + a1.x; o1.y = v3 + a1.y;
                *reinterpret_cast<float2*>(outF + p0) = o0;
                *reinterpret_cast<float2*>(outF + p1) = o1;
            }
        }
    }
}

// ---------------- host ----------------
extern "C" void kernel_launch(void* const* d_in, const int* in_sizes, int n_in,
                              void* d_out, int out_size)
{
    const float* x   = (const float*)d_in[0];
    const float* n1w = (const float*)d_in[1];
    const float* w1  = (const float*)d_in[2];
    const float* b1  = (const float*)d_in[3];
    const float* n2w = (const float*)d_in[4];
    const float* w2a = (const float*)d_in[5];
    const float* b2a = (const float*)d_in[6];
    const float* w2b = (const float*)d_in[7];
    const float* b2b = (const float*)d_in[8];
    float* out = (float*)d_out;

    void *p_s, *p_h, *p_a, *p_w1, *p_w2a, *p_w2b;
    float *out1, *yf;
    cudaGetSymbolAddress(&p_s, g_s);
    cudaGetSymbolAddress(&p_h, g_h);
    cudaGetSymbolAddress(&p_a, g_act);
    cudaGetSymbolAddress(&p_w1, g_w1T);
    cudaGetSymbolAddress(&p_w2a, g_w2aT);
    cudaGetSymbolAddress(&p_w2b, g_w2bT);
    cudaGetSymbolAddress((void**)&out1, g_out1);
    cudaGetSymbolAddress((void**)&yf, g_y);

    cudaFuncSetAttribute(mma_gemm<0>, cudaFuncAttributeMaxDynamicSharedMemorySize, SMTOT);
    cudaFuncSetAttribute(mma_gemm<1>, cudaFuncAttributeMaxDynamicSharedMemorySize, SMTOT);
    cudaFuncSetAttribute(mma_gemm<2>, cudaFuncAttributeMaxDynamicSharedMemorySize, SMTOT);

    // 1) y = rmsnorm(x)
    rmsnorm_kernel<false><<<Mtot, 256>>>(x, n1w, yf, nullptr);

    // 2) state = cumsum(y)/scaler -> fp16
    scan_partial<<<dim3(Bsz, NCHUNK, Cdim / 256), 256>>>();
    scan_prefix <<<dim3(Bsz, Cdim / 256),         256>>>();
    scan_final  <<<dim3(Bsz, NCHUNK, Cdim / 256), 256>>>();

    // 3) weight transpose -> fp16 [N,K]
    transpose_h<<<dim3(Cdim / 32, Cdim / 32), 256>>>(w1,  (f16*)p_w1,  Cdim, Cdim);
    transpose_h<<<dim3(Cdim / 32, Edim / 32), 256>>>(w2a, (f16*)p_w2a, Cdim, Edim);
    transpose_h<<<dim3(Edim / 32, Cdim / 32), 256>>>(w2b, (f16*)p_w2b, Edim, Cdim);

    // 4) out1 = sigmoid(state @ w1 + b1) * x
    mma_gemm<0><<<dim3(Cdim / 128, Mtot / 128), 256, SMTOT>>>(
        (f16*)p_s, (f16*)p_w1, b1, x, out1, nullptr, Cdim, Cdim);

    // 5) h = rmsnorm(out1) -> fp16
    rmsnorm_kernel<true><<<Mtot, 256>>>(out1, n2w, nullptr, (f16*)p_h);

    // 6) act = relu(h @ w2a + b2a) -> fp16
    mma_gemm<1><<<dim3(Edim / 128, Mtot / 128), 256, SMTOT>>>(
        (f16*)p_h, (f16*)p_w2a, b2a, nullptr, nullptr, (f16*)p_a, Edim, Cdim);

    // 7) out = act @ w2b + b2b + out1
    mma_gemm<2><<<dim3(Cdim / 128, Mtot / 128), 256, SMTOT>>>(
        (f16*)p_a, (f16*)p_w2b, b2b, out1, out, nullptr, Cdim, Edim);
}

// round 5
// speedup vs baseline: 7.3057x; 1.0308x over previous
#include <cuda_runtime.h>
#include <cuda.h>
#include <cuda_fp16.h>
#include <math.h>
#include <stdint.h>

#define Bsz   8
#define Tlen  2048
#define Cdim  1024
#define Edim  4096
#define Mtot  (Bsz * Tlen)       // 16384 tokens
#define CHUNK 64
#define NCHUNK (Tlen / CHUNK)    // 32

typedef __half f16;

// ---------------- scratch (no cudaMalloc allowed) ----------------
__device__ __align__(16) float g_y   [(size_t)Mtot * Cdim];
__device__ __align__(16) float g_out1[(size_t)Mtot * Cdim];
__device__ __align__(16) float g_csum[Bsz * NCHUNK * Cdim];

__device__ __align__(16) f16 g_s  [(size_t)Mtot * Cdim];   // state (fp16)
__device__ __align__(16) f16 g_h  [(size_t)Mtot * Cdim];   // rmsnorm2 out (fp16)
__device__ __align__(16) f16 g_act[(size_t)Mtot * Edim];   // relu hidden (fp16)

// transposed weights: [N, K] K-major fp16
__device__ __align__(16) f16 g_w1T [Cdim * Cdim];
__device__ __align__(16) f16 g_w2aT[(size_t)Edim * Cdim];
__device__ __align__(16) f16 g_w2bT[(size_t)Cdim * Edim];

// ---------------- helpers ----------------
__device__ __forceinline__ uint32_t smem_u32(const void* p) {
    uint32_t a;
    asm("{ .reg .u64 t; cvta.to.shared.u64 t, %1; cvt.u32.u64 %0, t; }" : "=r"(a) : "l"(p));
    return a;
}
__device__ __forceinline__ void cp16(uint32_t s, const void* g) {
    asm volatile("cp.async.cg.shared.global [%0], [%1], 16;" :: "r"(s), "l"(g) : "memory");
}
#define CP_COMMIT() asm volatile("cp.async.commit_group;" ::: "memory")
#define CP_WAIT(n)  asm volatile("cp.async.wait_group %0;" :: "n"(n) : "memory")

#define LDSM_X4(r, addr) \
    asm volatile("ldmatrix.sync.aligned.m8n8.x4.shared.b16 {%0,%1,%2,%3}, [%4];" \
        : "=r"((r)[0]), "=r"((r)[1]), "=r"((r)[2]), "=r"((r)[3]) : "r"(addr))

#define MMA_F16(d, a, b0, b1) \
    asm volatile("mma.sync.aligned.m16n8k16.row.col.f32.f16.f16.f32 " \
        "{%0,%1,%2,%3}, {%4,%5,%6,%7}, {%8,%9}, {%0,%1,%2,%3};" \
        : "+f"((d)[0]), "+f"((d)[1]), "+f"((d)[2]), "+f"((d)[3]) \
        : "r"((a)[0]), "r"((a)[1]), "r"((a)[2]), "r"((a)[3]), "r"(b0), "r"(b1))

// ---------------- fused prep: rmsnorm1 (fp32 out) + 3 weight transposes ----------------
__device__ __forceinline__ void rmsnorm_row_f32(const float* __restrict__ x,
                                                const float* __restrict__ w,
                                                float* __restrict__ y,
                                                int row, float* sh)
{
    const float4* xr = reinterpret_cast<const float4*>(x) + (size_t)row * (Cdim / 4);
    float4 v = xr[threadIdx.x];
    float ss = v.x * v.x + v.y * v.y + v.z * v.z + v.w * v.w;
    #pragma unroll
    for (int o = 16; o; o >>= 1) ss += __shfl_xor_sync(0xffffffffu, ss, o);
    int wid = threadIdx.x >> 5, lid = threadIdx.x & 31;
    if (lid == 0) sh[wid] = ss;
    __syncthreads();
    if (threadIdx.x < 8) {
        float t = sh[threadIdx.x];
        t += __shfl_xor_sync(0xffu, t, 1);
        t += __shfl_xor_sync(0xffu, t, 2);
        t += __shfl_xor_sync(0xffu, t, 4);
        if (threadIdx.x == 0) sh[0] = t;
    }
    __syncthreads();
    float inv = rsqrtf(sh[0] * (1.0f / Cdim) + 1e-6f);
    float4 wv = reinterpret_cast<const float4*>(w)[threadIdx.x];
    float4 o;
    o.x = v.x * inv * wv.x; o.y = v.y * inv * wv.y;
    o.z = v.z * inv * wv.z; o.w = v.w * inv * wv.w;
    reinterpret_cast<float4*>(y)[(size_t)row * (Cdim / 4) + threadIdx.x] = o;
}

__device__ __forceinline__ void transpose_tile(const float* __restrict__ in,
                                               f16* __restrict__ o16,
                                               int K, int N, int bx, int by, float* sh)
{
    // sh used as [32][33]
    int k0 = bx * 32, n0 = by * 32;
    int x = threadIdx.x & 31, y = threadIdx.x >> 5;
    #pragma unroll
    for (int i = y; i < 32; i += 8)
        sh[i * 33 + x] = in[(size_t)(k0 + i) * N + n0 + x];
    __syncthreads();
    #pragma unroll
    for (int i = y; i < 32; i += 8)
        o16[(size_t)(n0 + i) * K + k0 + x] = __float2half(sh[x * 33 + i]);
}

#define TW1  (Cdim / 32) * (Cdim / 32)   // 1024
#define TW2A (Cdim / 32) * (Edim / 32)   // 4096
#define TW2B (Edim / 32) * (Cdim / 32)   // 4096

__global__ void __launch_bounds__(256) prep_kernel(const float* __restrict__ x,
                                                   const float* __restrict__ n1w,
                                                   const float* __restrict__ w1,
                                                   const float* __restrict__ w2a,
                                                   const float* __restrict__ w2b)
{
    __shared__ float sh[32 * 33];
    int bid = blockIdx.x;
    if (bid < Mtot) { rmsnorm_row_f32(x, n1w, g_y, bid, sh); return; }
    bid -= Mtot;
    if (bid < TW1)  { transpose_tile(w1,  g_w1T,  Cdim, Cdim, bid & 31, bid >> 5, sh); return; }
    bid -= TW1;
    if (bid < TW2A) { transpose_tile(w2a, g_w2aT, Cdim, Edim, bid & 31, bid >> 5, sh); return; }
    bid -= TW2A;
    transpose_tile(w2b, g_w2bT, Edim, Cdim, bid & 127, bid >> 7, sh);
}

// ---------------- standalone rmsnorm -> fp16 (for h = rmsnorm(out1)) ----------------
__global__ void __launch_bounds__(256) rmsnorm_h_kernel(const float* __restrict__ x,
                                                        const float* __restrict__ w,
                                                        f16* __restrict__ yH)
{
    __shared__ float sh[8];
    int row = blockIdx.x;
    const float4* xr = reinterpret_cast<const float4*>(x) + (size_t)row * (Cdim / 4);
    float4 v = xr[threadIdx.x];
    float ss = v.x * v.x + v.y * v.y + v.z * v.z + v.w * v.w;
    #pragma unroll
    for (int o = 16; o; o >>= 1) ss += __shfl_xor_sync(0xffffffffu, ss, o);
    int wid = threadIdx.x >> 5, lid = threadIdx.x & 31;
    if (lid == 0) sh[wid] = ss;
    __syncthreads();
    if (threadIdx.x < 8) {
        float t = sh[threadIdx.x];
        t += __shfl_xor_sync(0xffu, t, 1);
        t += __shfl_xor_sync(0xffu, t, 2);
        t += __shfl_xor_sync(0xffu, t, 4);
        if (threadIdx.x == 0) sh[0] = t;
    }
    __syncthreads();
    float inv = rsqrtf(sh[0] * (1.0f / Cdim) + 1e-6f);
    float4 wv = reinterpret_cast<const float4*>(w)[threadIdx.x];
    size_t base = (size_t)row * Cdim + threadIdx.x * 4;
    __half2 p0, p1;
    p0.x = __float2half(v.x * inv * wv.x);
    p0.y = __float2half(v.y * inv * wv.y);
    p1.x = __float2half(v.z * inv * wv.z);
    p1.y = __float2half(v.w * inv * wv.w);
    *reinterpret_cast<__half2*>(yH + base)     = p0;
    *reinterpret_cast<__half2*>(yH + base + 2) = p1;
}

// ---------------- chunked scan (float2 per thread) ----------------
#define C2 (Cdim / 2)

__global__ void __launch_bounds__(256) scan_partial()
{
    int b = blockIdx.x, ch = blockIdx.y;
    int c2 = blockIdx.z * 256 + threadIdx.x;
    const float2* p = reinterpret_cast<const float2*>(g_y)
                    + (size_t)(b * Tlen + ch * CHUNK) * C2 + c2;
    float2 s = make_float2(0.f, 0.f);
    #pragma unroll 8
    for (int t = 0; t < CHUNK; t++) {
        float2 v = p[(size_t)t * C2];
        s.x += v.x; s.y += v.y;
    }
    reinterpret_cast<float2*>(g_csum)[(b * NCHUNK + ch) * C2 + c2] = s;
}

__global__ void __launch_bounds__(256) scan_prefix()
{
    int b = blockIdx.x;
    int c2 = blockIdx.y * 256 + threadIdx.x;
    float2* buf = reinterpret_cast<float2*>(g_csum);
    float2 run = make_float2(0.f, 0.f);
    #pragma unroll
    for (int ch = 0; ch < NCHUNK; ch++) {
        int idx = (b * NCHUNK + ch) * C2 + c2;
        float2 v = buf[idx];
        buf[idx] = run;
        run.x += v.x; run.y += v.y;
    }
}

__global__ void __launch_bounds__(256) scan_final()
{
    int b = blockIdx.x, ch = blockIdx.y;
    int c2 = blockIdx.z * 256 + threadIdx.x;
    float2 run = reinterpret_cast<const float2*>(g_csum)[(b * NCHUNK + ch) * C2 + c2];
    const float2* p = reinterpret_cast<const float2*>(g_y)
                    + (size_t)(b * Tlen + ch * CHUNK) * C2 + c2;
    __half2* o = reinterpret_cast<__half2*>(g_s)
               + (size_t)(b * Tlen + ch * CHUNK) * C2 + c2;
    int tg0 = ch * CHUNK;
    #pragma unroll 8
    for (int t = 0; t < CHUNK; t++) {
        float2 v = p[(size_t)t * C2];
        run.x += v.x; run.y += v.y;
        float tg = (float)(tg0 + t);
        float rs = 1.0f / (0.5f * (tg + 1.f) * (tg + 2.f));
        __half2 hv;
        hv.x = __float2half(run.x * rs);
        hv.y = __float2half(run.y * rs);
        o[(size_t)t * C2] = hv;
    }
}

// ---------------- fp16 HMMA GEMM: 128x128x64 tiles, 3-stage cp.async ----------------
// A: [M,K] row-major f16, B: [N,K] row-major f16 -> C[M,N]
// EPI 0: outF = sigmoid(acc+bias) * aux
// EPI 1: outH = (f16) relu(acc+bias)
// EPI 2: outF = acc + bias + aux
#define BKt    64
#define STG    3
#define TILEB  32768                // A 16KB + B 16KB per stage
#define SMTOT  (STG * TILEB)

__device__ __forceinline__ void load_tile64(const f16* __restrict__ A,
                                            const f16* __restrict__ B,
                                            int bm, int bn, int koff, int K,
                                            uint32_t sbase, int stage, int tid)
{
    uint32_t sA = sbase + stage * TILEB;
    uint32_t sB = sA + 16384;
    #pragma unroll
    for (int i = 0; i < 4; i++) {
        int idx = tid + i * 256;          // 0..1023
        int row = idx >> 3, ch = idx & 7;
        int chs = ch ^ (row & 7);         // 128B-row swizzle
        uint32_t so = (uint32_t)(row * 128 + chs * 16);
        cp16(sA + so, A + (size_t)(bm + row) * K + koff + ch * 8);
        cp16(sB + so, B + (size_t)(bn + row) * K + koff + ch * 8);
    }
}

template<int EPI>
__global__ void __launch_bounds__(256, 2) mma_gemm(
    const f16* __restrict__ Ag, const f16* __restrict__ Bg,
    const float* __restrict__ bias, const float* __restrict__ aux,
    float* __restrict__ outF, f16* __restrict__ outH,
    int N, int K)
{
    extern __shared__ __align__(16) char smem[];
    uint32_t sbase = smem_u32(smem);
    int tid = threadIdx.x, wid = tid >> 5, lane = tid & 31;
    int bm = blockIdx.y * 128, bn = blockIdx.x * 128;
    int wm = (wid >> 2) * 64, wn = (wid & 3) * 32;

    int nkt = K / BKt;

    float acc[4][4][4] = {};

    // prologue: prefetch 2 tiles
    load_tile64(Ag, Bg, bm, bn, 0,   K, sbase, 0, tid); CP_COMMIT();
    load_tile64(Ag, Bg, bm, bn, BKt, K, sbase, 1, tid); CP_COMMIT();

    // ldmatrix lane constants
    int l8 = lane & 7;
    int aRow  = wm + l8 + ((lane >> 3) & 1) * 8;   // + mf*16
    int aCHi  = (lane >> 4) & 1;
    int aXor  = aRow & 7;
    int bRow  = wn + l8 + ((lane >> 4) & 1) * 8;   // + g*16
    int bCHi  = (lane >> 3) & 1;
    int bXor  = bRow & 7;

    int cs = 0, ls = 2;   // compute stage, load stage
    for (int kk = 0; kk < nkt; kk++) {
        if (kk + 1 < nkt) { CP_WAIT(1); } else { CP_WAIT(0); }
        __syncthreads();

        if (kk + 2 < nkt) {
            load_tile64(Ag, Bg, bm, bn, (kk + 2) * BKt, K, sbase, ls, tid);
            CP_COMMIT();
            if (++ls == STG) ls = 0;
        }

        uint32_t sA = sbase + cs * TILEB;
        uint32_t sB = sA + 16384;
        if (++cs == STG) cs = 0;

        #pragma unroll
        for (int ks = 0; ks < 4; ks++) {
            uint32_t a[4][4];
            #pragma unroll
            for (int mf = 0; mf < 4; mf++) {
                uint32_t addr = sA + (uint32_t)((aRow + mf * 16) * 128
                              + (((ks * 2 + aCHi) ^ aXor) * 16));
                LDSM_X4(a[mf], addr);
            }
            uint32_t b[4][2];
            #pragma unroll
            for (int g = 0; g < 2; g++) {
                uint32_t r[4];
                uint32_t addr = sB + (uint32_t)((bRow + g * 16) * 128
                              + (((ks * 2 + bCHi) ^ bXor) * 16));
                LDSM_X4(r, addr);
                b[2*g][0] = r[0]; b[2*g][1] = r[1];
                b[2*g+1][0] = r[2]; b[2*g+1][1] = r[3];
            }
            #pragma unroll
            for (int mf = 0; mf < 4; mf++)
                #pragma unroll
                for (int nf = 0; nf < 4; nf++)
                    MMA_F16(acc[mf][nf], a[mf], b[nf][0], b[nf][1]);
        }
    }

    // epilogue
    int mrow = bm + wm + (lane >> 2);
    int ncol = bn + wn + (lane & 3) * 2;
    #pragma unroll
    for (int mf = 0; mf < 4; mf++) {
        int r0 = mrow + mf * 16;
        #pragma unroll
        for (int nf = 0; nf < 4; nf++) {
            int n = ncol + nf * 8;
            float bz0 = bias[n], bz1 = bias[n + 1];
            float v0 = acc[mf][nf][0] + bz0;
            float v1 = acc[mf][nf][1] + bz1;
            float v2 = acc[mf][nf][2] + bz0;
            float v3 = acc[mf][nf][3] + bz1;
            size_t p0 = (size_t)r0 * N + n;
            size_t p1 = (size_t)(r0 + 8) * N + n;
            if (EPI == 0) {
                float2 a0 = *reinterpret_cast<const float2*>(aux + p0);
                float2 a1 = *reinterpret_cast<const float2*>(aux + p1);
                v0 = a0.x * (1.f / (1.f + __expf(-v0)));
                v1 = a0.y * (1.f / (1.f + __expf(-v1)));
                v2 = a1.x * (1.f / (1.f + __expf(-v2)));
                v3 = a1.y * (1.f / (1.f + __expf(-v3)));
                float2 o0; o0.x = v0; o0.y = v1;
                float2 o1; o1.x = v2; o1.y = v3;
                *reinterpret_cast<float2*>(outF + p0) = o0;
                *reinterpret_cast<float2*>(outF + p1) = o1;
            } else if (EPI == 1) {
                __half2 h0, h1;
                h0.x = __float2half(fmaxf(v0, 0.f));
                h0.y = __float2half(fmaxf(v1, 0.f));
                h1.x = __float2half(fmaxf(v2, 0.f));
                h1.y = __float2half(fmaxf(v3, 0.f));
                *reinterpret_cast<__half2*>(outH + p0) = h0;
                *reinterpret_cast<__half2*>(outH + p1) = h1;
            } else {
                float2 a0 = *reinterpret_cast<const float2*>(aux + p0);
                float2 a1 = *reinterpret_cast<const float2*>(aux + p1);
                float2 o0; o0.x = v0 + a0.x; o0.y = v1 + a0.y;
                float2 o1; o1.x = v2 + a1.x; o1.y = v3 + a1.y;
                *reinterpret_cast<float2*>(outF + p0) = o0;
                *reinterpret_cast<float2*>(outF + p1) = o1;
            }
        }
    }
}

// ---------------- host ----------------
extern "C" void kernel_launch(void* const* d_in, const int* in_sizes, int n_in,
                              void* d_out, int out_size)
{
    const float* x   = (const float*)d_in[0];
    const float* n1w = (const float*)d_in[1];
    const float* w1  = (const float*)d_in[2];
    const float* b1  = (const float*)d_in[3];
    const float* n2w = (const float*)d_in[4];
    const float* w2a = (const float*)d_in[5];
    const float* b2a = (const float*)d_in[6];
    const float* w2b = (const float*)d_in[7];
    const float* b2b = (const float*)d_in[8];
    float* out = (float*)d_out;

    void *p_s, *p_h, *p_a, *p_w1, *p_w2a, *p_w2b;
    float *out1;
    cudaGetSymbolAddress(&p_s, g_s);
    cudaGetSymbolAddress(&p_h, g_h);
    cudaGetSymbolAddress(&p_a, g_act);
    cudaGetSymbolAddress(&p_w1, g_w1T);
    cudaGetSymbolAddress(&p_w2a, g_w2aT);
    cudaGetSymbolAddress(&p_w2b, g_w2bT);
    cudaGetSymbolAddress((void**)&out1, g_out1);

    cudaFuncSetAttribute(mma_gemm<0>, cudaFuncAttributeMaxDynamicSharedMemorySize, SMTOT);
    cudaFuncSetAttribute(mma_gemm<1>, cudaFuncAttributeMaxDynamicSharedMemorySize, SMTOT);
    cudaFuncSetAttribute(mma_gemm<2>, cudaFuncAttributeMaxDynamicSharedMemorySize, SMTOT);

    // 1) fused: y = rmsnorm(x) + transpose(w1, w2a, w2b) -> fp16 [N,K]
    prep_kernel<<<Mtot + TW1 + TW2A + TW2B, 256>>>(x, n1w, w1, w2a, w2b);

    // 2) state = cumsum(y)/scaler -> fp16
    scan_partial<<<dim3(Bsz, NCHUNK, 2), 256>>>();
    scan_prefix <<<dim3(Bsz, 2),         256>>>();
    scan_final  <<<dim3(Bsz, NCHUNK, 2), 256>>>();

    // 3) out1 = sigmoid(state @ w1 + b1) * x
    mma_gemm<0><<<dim3(Cdim / 128, Mtot / 128), 256, SMTOT>>>(
        (f16*)p_s, (f16*)p_w1, b1, x, out1, nullptr, Cdim, Cdim);

    // 4) h = rmsnorm(out1) -> fp16
    rmsnorm_h_kernel<<<Mtot, 256>>>(out1, n2w, (f16*)p_h);

    // 5) act = relu(h @ w2a + b2a) -> fp16
    mma_gemm<1><<<dim3(Edim / 128, Mtot / 128), 256, SMTOT>>>(
        (f16*)p_h, (f16*)p_w2a, b2a, nullptr, nullptr, (f16*)p_a, Edim, Cdim);

    // 6) out = act @ w2b + b2b + out1
    mma_gemm<2><<<dim3(Cdim / 128, Mtot / 128), 256, SMTOT>>>(
        (f16*)p_a, (f16*)p_w2b, b2b, out1, out, nullptr, Cdim, Edim);
}

// round 6
// speedup vs baseline: 7.5526x; 1.0338x over previous
#include <cuda_runtime.h>
#include <cuda.h>
#include <cuda_fp16.h>
#include <math.h>
#include <stdint.h>

#define Bsz   8
#define Tlen  2048
#define Cdim  1024
#define Edim  4096
#define Mtot  (Bsz * Tlen)       // 16384 tokens
#define CHUNK 32
#define NCHUNK (Tlen / CHUNK)    // 64

typedef __half f16;

// ---------------- scratch (no cudaMalloc allowed) ----------------
__device__ __align__(16) f16   g_y   [(size_t)Mtot * Cdim];   // rmsnorm1 out (fp16)
__device__ __align__(16) float g_out1[(size_t)Mtot * Cdim];   // gate*x (fp32, residual)
__device__ __align__(16) float g_csum[Bsz * NCHUNK * Cdim];

__device__ __align__(16) f16 g_s  [(size_t)Mtot * Cdim];   // state (fp16)
__device__ __align__(16) f16 g_h  [(size_t)Mtot * Cdim];   // rmsnorm2 out (fp16)
__device__ __align__(16) f16 g_act[(size_t)Mtot * Edim];   // relu hidden (fp16)

// transposed weights: [N, K] K-major fp16
__device__ __align__(16) f16 g_w1T [Cdim * Cdim];
__device__ __align__(16) f16 g_w2aT[(size_t)Edim * Cdim];
__device__ __align__(16) f16 g_w2bT[(size_t)Cdim * Edim];

// ---------------- helpers ----------------
__device__ __forceinline__ uint32_t smem_u32(const void* p) {
    uint32_t a;
    asm("{ .reg .u64 t; cvta.to.shared.u64 t, %1; cvt.u32.u64 %0, t; }" : "=r"(a) : "l"(p));
    return a;
}
__device__ __forceinline__ void cp16(uint32_t s, const void* g) {
    asm volatile("cp.async.cg.shared.global [%0], [%1], 16;" :: "r"(s), "l"(g) : "memory");
}
#define CP_COMMIT() asm volatile("cp.async.commit_group;" ::: "memory")
#define CP_WAIT(n)  asm volatile("cp.async.wait_group %0;" :: "n"(n) : "memory")

#define LDSM_X4(r, addr) \
    asm volatile("ldmatrix.sync.aligned.m8n8.x4.shared.b16 {%0,%1,%2,%3}, [%4];" \
        : "=r"((r)[0]), "=r"((r)[1]), "=r"((r)[2]), "=r"((r)[3]) : "r"(addr))

#define MMA_F16(d, a, b0, b1) \
    asm volatile("mma.sync.aligned.m16n8k16.row.col.f32.f16.f16.f32 " \
        "{%0,%1,%2,%3}, {%4,%5,%6,%7}, {%8,%9}, {%0,%1,%2,%3};" \
        : "+f"((d)[0]), "+f"((d)[1]), "+f"((d)[2]), "+f"((d)[3]) \
        : "r"((a)[0]), "r"((a)[1]), "r"((a)[2]), "r"((a)[3]), "r"(b0), "r"(b1))

// ---------------- fused prep: rmsnorm1 (fp16 out) + 3 weight transposes ----------------
__device__ __forceinline__ void rmsnorm_row_h(const float* __restrict__ x,
                                              const float* __restrict__ w,
                                              f16* __restrict__ y,
                                              int row, float* sh)
{
    const float4* xr = reinterpret_cast<const float4*>(x) + (size_t)row * (Cdim / 4);
    float4 v = xr[threadIdx.x];
    float ss = v.x * v.x + v.y * v.y + v.z * v.z + v.w * v.w;
    #pragma unroll
    for (int o = 16; o; o >>= 1) ss += __shfl_xor_sync(0xffffffffu, ss, o);
    int wid = threadIdx.x >> 5, lid = threadIdx.x & 31;
    if (lid == 0) sh[wid] = ss;
    __syncthreads();
    if (threadIdx.x < 8) {
        float t = sh[threadIdx.x];
        t += __shfl_xor_sync(0xffu, t, 1);
        t += __shfl_xor_sync(0xffu, t, 2);
        t += __shfl_xor_sync(0xffu, t, 4);
        if (threadIdx.x == 0) sh[0] = t;
    }
    __syncthreads();
    float inv = rsqrtf(sh[0] * (1.0f / Cdim) + 1e-6f);
    float4 wv = reinterpret_cast<const float4*>(w)[threadIdx.x];
    __half2 p0, p1;
    p0.x = __float2half(v.x * inv * wv.x);
    p0.y = __float2half(v.y * inv * wv.y);
    p1.x = __float2half(v.z * inv * wv.z);
    p1.y = __float2half(v.w * inv * wv.w);
    size_t base = (size_t)row * Cdim + threadIdx.x * 4;
    *reinterpret_cast<__half2*>(y + base)     = p0;
    *reinterpret_cast<__half2*>(y + base + 2) = p1;
}

__device__ __forceinline__ void transpose_tile(const float* __restrict__ in,
                                               f16* __restrict__ o16,
                                               int K, int N, int bx, int by, float* sh)
{
    int k0 = bx * 32, n0 = by * 32;
    int x = threadIdx.x & 31, y = threadIdx.x >> 5;
    #pragma unroll
    for (int i = y; i < 32; i += 8)
        sh[i * 33 + x] = in[(size_t)(k0 + i) * N + n0 + x];
    __syncthreads();
    #pragma unroll
    for (int i = y; i < 32; i += 8)
        o16[(size_t)(n0 + i) * K + k0 + x] = __float2half(sh[x * 33 + i]);
}

#define TW1  (Cdim / 32) * (Cdim / 32)   // 1024
#define TW2A (Cdim / 32) * (Edim / 32)   // 4096
#define TW2B (Edim / 32) * (Cdim / 32)   // 4096

__global__ void __launch_bounds__(256) prep_kernel(const float* __restrict__ x,
                                                   const float* __restrict__ n1w,
                                                   const float* __restrict__ w1,
                                                   const float* __restrict__ w2a,
                                                   const float* __restrict__ w2b)
{
    __shared__ float sh[32 * 33];
    int bid = blockIdx.x;
    if (bid < Mtot) { rmsnorm_row_h(x, n1w, g_y, bid, sh); return; }
    bid -= Mtot;
    if (bid < TW1)  { transpose_tile(w1,  g_w1T,  Cdim, Cdim, bid & 31, bid >> 5, sh); return; }
    bid -= TW1;
    if (bid < TW2A) { transpose_tile(w2a, g_w2aT, Cdim, Edim, bid & 31, bid >> 5, sh); return; }
    bid -= TW2A;
    transpose_tile(w2b, g_w2bT, Edim, Cdim, bid & 127, bid >> 7, sh);
}

// ---------------- standalone rmsnorm -> fp16 (h = rmsnorm(out1)) ----------------
__global__ void __launch_bounds__(256) rmsnorm_h_kernel(const float* __restrict__ x,
                                                        const float* __restrict__ w,
                                                        f16* __restrict__ yH)
{
    __shared__ float sh[8];
    int row = blockIdx.x;
    const float4* xr = reinterpret_cast<const float4*>(x) + (size_t)row * (Cdim / 4);
    float4 v = xr[threadIdx.x];
    float ss = v.x * v.x + v.y * v.y + v.z * v.z + v.w * v.w;
    #pragma unroll
    for (int o = 16; o; o >>= 1) ss += __shfl_xor_sync(0xffffffffu, ss, o);
    int wid = threadIdx.x >> 5, lid = threadIdx.x & 31;
    if (lid == 0) sh[wid] = ss;
    __syncthreads();
    if (threadIdx.x < 8) {
        float t = sh[threadIdx.x];
        t += __shfl_xor_sync(0xffu, t, 1);
        t += __shfl_xor_sync(0xffu, t, 2);
        t += __shfl_xor_sync(0xffu, t, 4);
        if (threadIdx.x == 0) sh[0] = t;
    }
    __syncthreads();
    float inv = rsqrtf(sh[0] * (1.0f / Cdim) + 1e-6f);
    float4 wv = reinterpret_cast<const float4*>(w)[threadIdx.x];
    size_t base = (size_t)row * Cdim + threadIdx.x * 4;
    __half2 p0, p1;
    p0.x = __float2half(v.x * inv * wv.x);
    p0.y = __float2half(v.y * inv * wv.y);
    p1.x = __float2half(v.z * inv * wv.z);
    p1.y = __float2half(v.w * inv * wv.w);
    *reinterpret_cast<__half2*>(yH + base)     = p0;
    *reinterpret_cast<__half2*>(yH + base + 2) = p1;
}

// ---------------- chunked scan (fp16 input, fp32 accumulate, 2 channels/thread) ----------------
#define C2 (Cdim / 2)

__global__ void __launch_bounds__(256) scan_partial()
{
    int b = blockIdx.x, ch = blockIdx.y;
    int c2 = blockIdx.z * 256 + threadIdx.x;
    const __half2* p = reinterpret_cast<const __half2*>(g_y)
                     + (size_t)(b * Tlen + ch * CHUNK) * C2 + c2;
    float2 s = make_float2(0.f, 0.f);
    #pragma unroll
    for (int t = 0; t < CHUNK; t++) {
        float2 v = __half22float2(p[(size_t)t * C2]);
        s.x += v.x; s.y += v.y;
    }
    reinterpret_cast<float2*>(g_csum)[(b * NCHUNK + ch) * C2 + c2] = s;
}

__global__ void __launch_bounds__(256) scan_prefix()
{
    int b = blockIdx.x;
    int c2 = blockIdx.y * 256 + threadIdx.x;
    float2* buf = reinterpret_cast<float2*>(g_csum);
    float2 run = make_float2(0.f, 0.f);
    #pragma unroll
    for (int ch = 0; ch < NCHUNK; ch++) {
        int idx = (b * NCHUNK + ch) * C2 + c2;
        float2 v = buf[idx];
        buf[idx] = run;
        run.x += v.x; run.y += v.y;
    }
}

__global__ void __launch_bounds__(256) scan_final()
{
    int b = blockIdx.x, ch = blockIdx.y;
    int c2 = blockIdx.z * 256 + threadIdx.x;
    float2 run = reinterpret_cast<const float2*>(g_csum)[(b * NCHUNK + ch) * C2 + c2];
    const __half2* p = reinterpret_cast<const __half2*>(g_y)
                     + (size_t)(b * Tlen + ch * CHUNK) * C2 + c2;
    __half2* o = reinterpret_cast<__half2*>(g_s)
               + (size_t)(b * Tlen + ch * CHUNK) * C2 + c2;
    int tg0 = ch * CHUNK;
    #pragma unroll
    for (int t = 0; t < CHUNK; t++) {
        float2 v = __half22float2(p[(size_t)t * C2]);
        run.x += v.x; run.y += v.y;
        float tg = (float)(tg0 + t);
        float rs = 1.0f / (0.5f * (tg + 1.f) * (tg + 2.f));
        __half2 hv;
        hv.x = __float2half(run.x * rs);
        hv.y = __float2half(run.y * rs);
        o[(size_t)t * C2] = hv;
    }
}

// ---------------- fp16 HMMA GEMM: 128x128x64 tiles, 3-stage cp.async ----------------
// A: [M,K] row-major f16, B: [N,K] row-major f16 -> C[M,N]
// EPI 0: outF = sigmoid(acc+bias) * aux
// EPI 1: outH = (f16) relu(acc+bias)
// EPI 2: outF = acc + bias + aux
#define BKt    64
#define STG    3
#define TILEB  32768                // A 16KB + B 16KB per stage
#define SMTOT  (STG * TILEB)

__device__ __forceinline__ void load_tile64(const f16* __restrict__ A,
                                            const f16* __restrict__ B,
                                            int bm, int bn, int koff, int K,
                                            uint32_t sbase, int stage, int tid)
{
    uint32_t sA = sbase + stage * TILEB;
    uint32_t sB = sA + 16384;
    #pragma unroll
    for (int i = 0; i < 4; i++) {
        int idx = tid + i * 256;          // 0..1023
        int row = idx >> 3, ch = idx & 7;
        int chs = ch ^ (row & 7);         // 128B-row swizzle
        uint32_t so = (uint32_t)(row * 128 + chs * 16);
        cp16(sA + so, A + (size_t)(bm + row) * K + koff + ch * 8);
        cp16(sB + so, B + (size_t)(bn + row) * K + koff + ch * 8);
    }
}

template<int EPI>
__global__ void __launch_bounds__(256, 2) mma_gemm(
    const f16* __restrict__ Ag, const f16* __restrict__ Bg,
    const float* __restrict__ bias, const float* __restrict__ aux,
    float* __restrict__ outF, f16* __restrict__ outH,
    int N, int K)
{
    extern __shared__ __align__(16) char smem[];
    uint32_t sbase = smem_u32(smem);
    int tid = threadIdx.x, wid = tid >> 5, lane = tid & 31;
    int bm = blockIdx.y * 128, bn = blockIdx.x * 128;
    int wm = (wid >> 2) * 64, wn = (wid & 3) * 32;

    int nkt = K / BKt;

    float acc[4][4][4] = {};

    // prologue: prefetch 2 tiles
    load_tile64(Ag, Bg, bm, bn, 0,   K, sbase, 0, tid); CP_COMMIT();
    load_tile64(Ag, Bg, bm, bn, BKt, K, sbase, 1, tid); CP_COMMIT();

    // ldmatrix lane constants
    int l8 = lane & 7;
    int aRow  = wm + l8 + ((lane >> 3) & 1) * 8;   // + mf*16
    int aCHi  = (lane >> 4) & 1;
    int aXor  = aRow & 7;
    int bRow  = wn + l8 + ((lane >> 4) & 1) * 8;   // + g*16
    int bCHi  = (lane >> 3) & 1;
    int bXor  = bRow & 7;

    int cs = 0, ls = 2;   // compute stage, load stage
    for (int kk = 0; kk < nkt; kk++) {
        if (kk + 1 < nkt) { CP_WAIT(1); } else { CP_WAIT(0); }
        __syncthreads();

        if (kk + 2 < nkt) {
            load_tile64(Ag, Bg, bm, bn, (kk + 2) * BKt, K, sbase, ls, tid);
            CP_COMMIT();
            if (++ls == STG) ls = 0;
        }

        uint32_t sA = sbase + cs * TILEB;
        uint32_t sB = sA + 16384;
        if (++cs == STG) cs = 0;

        #pragma unroll
        for (int ks = 0; ks < 4; ks++) {
            uint32_t a[4][4];
            #pragma unroll
            for (int mf = 0; mf < 4; mf++) {
                uint32_t addr = sA + (uint32_t)((aRow + mf * 16) * 128
                              + (((ks * 2 + aCHi) ^ aXor) * 16));
                LDSM_X4(a[mf], addr);
            }
            uint32_t b[4][2];
            #pragma unroll
            for (int g = 0; g < 2; g++) {
                uint32_t r[4];
                uint32_t addr = sB + (uint32_t)((bRow + g * 16) * 128
                              + (((ks * 2 + bCHi) ^ bXor) * 16));
                LDSM_X4(r, addr);
                b[2*g][0] = r[0]; b[2*g][1] = r[1];
                b[2*g+1][0] = r[2]; b[2*g+1][1] = r[3];
            }
            #pragma unroll
            for (int mf = 0; mf < 4; mf++)
                #pragma unroll
                for (int nf = 0; nf < 4; nf++)
                    MMA_F16(acc[mf][nf], a[mf], b[nf][0], b[nf][1]);
        }
    }

    // epilogue
    int mrow = bm + wm + (lane >> 2);
    int ncol = bn + wn + (lane & 3) * 2;
    #pragma unroll
    for (int mf = 0; mf < 4; mf++) {
        int r0 = mrow + mf * 16;
        #pragma unroll
        for (int nf = 0; nf < 4; nf++) {
            int n = ncol + nf * 8;
            float bz0 = bias[n], bz1 = bias[n + 1];
            float v0 = acc[mf][nf][0] + bz0;
            float v1 = acc[mf][nf][1] + bz1;
            float v2 = acc[mf][nf][2] + bz0;
            float v3 = acc[mf][nf][3] + bz1;
            size_t p0 = (size_t)r0 * N + n;
            size_t p1 = (size_t)(r0 + 8) * N + n;
            if (EPI == 0) {
                float2 a0 = *reinterpret_cast<const float2*>(aux + p0);
                float2 a1 = *reinterpret_cast<const float2*>(aux + p1);
                v0 = a0.x * (1.f / (1.f + __expf(-v0)));
                v1 = a0.y * (1.f / (1.f + __expf(-v1)));
                v2 = a1.x * (1.f / (1.f + __expf(-v2)));
                v3 = a1.y * (1.f / (1.f + __expf(-v3)));
                float2 o0; o0.x = v0; o0.y = v1;
                float2 o1; o1.x = v2; o1.y = v3;
                *reinterpret_cast<float2*>(outF + p0) = o0;
                *reinterpret_cast<float2*>(outF + p1) = o1;
            } else if (EPI == 1) {
                __half2 h0, h1;
                h0.x = __float2half(fmaxf(v0, 0.f));
                h0.y = __float2half(fmaxf(v1, 0.f));
                h1.x = __float2half(fmaxf(v2, 0.f));
                h1.y = __float2half(fmaxf(v3, 0.f));
                *reinterpret_cast<__half2*>(outH + p0) = h0;
                *reinterpret_cast<__half2*>(outH + p1) = h1;
            } else {
                float2 a0 = *reinterpret_cast<const float2*>(aux + p0);
                float2 a1 = *reinterpret_cast<const float2*>(aux + p1);
                float2 o0; o0.x = v0 + a0.x; o0.y = v1 + a0.y;
                float2 o1; o1.x = v2 + a1.x; o1.y = v3 + a1.y;
                *reinterpret_cast<float2*>(outF + p0) = o0;
                *reinterpret_cast<float2*>(outF + p1) = o1;
            }
        }
    }
}

// ---------------- host ----------------
extern "C" void kernel_launch(void* const* d_in, const int* in_sizes, int n_in,
                              void* d_out, int out_size)
{
    const float* x   = (const float*)d_in[0];
    const float* n1w = (const float*)d_in[1];
    const float* w1  = (const float*)d_in[2];
    const float* b1  = (const float*)d_in[3];
    const float* n2w = (const float*)d_in[4];
    const float* b2a = (const float*)d_in[6];
    const float* w2a = (const float*)d_in[5];
    const float* w2b = (const float*)d_in[7];
    const float* b2b = (const float*)d_in[8];
    float* out = (float*)d_out;

    void *p_s, *p_h, *p_a, *p_w1, *p_w2a, *p_w2b;
    float *out1;
    cudaGetSymbolAddress(&p_s, g_s);
    cudaGetSymbolAddress(&p_h, g_h);
    cudaGetSymbolAddress(&p_a, g_act);
    cudaGetSymbolAddress(&p_w1, g_w1T);
    cudaGetSymbolAddress(&p_w2a, g_w2aT);
    cudaGetSymbolAddress(&p_w2b, g_w2bT);
    cudaGetSymbolAddress((void**)&out1, g_out1);

    cudaFuncSetAttribute(mma_gemm<0>, cudaFuncAttributeMaxDynamicSharedMemorySize, SMTOT);
    cudaFuncSetAttribute(mma_gemm<1>, cudaFuncAttributeMaxDynamicSharedMemorySize, SMTOT);
    cudaFuncSetAttribute(mma_gemm<2>, cudaFuncAttributeMaxDynamicSharedMemorySize, SMTOT);

    // 1) fused: y = rmsnorm(x) (fp16) + transpose(w1, w2a, w2b) -> fp16 [N,K]
    prep_kernel<<<Mtot + TW1 + TW2A + TW2B, 256>>>(x, n1w, w1, w2a, w2b);

    // 2) state = cumsum(y)/scaler -> fp16
    scan_partial<<<dim3(Bsz, NCHUNK, 2), 256>>>();
    scan_prefix <<<dim3(Bsz, 2),         256>>>();
    scan_final  <<<dim3(Bsz, NCHUNK, 2), 256>>>();

    // 3) out1 = sigmoid(state @ w1 + b1) * x
    mma_gemm<0><<<dim3(Cdim / 128, Mtot / 128), 256, SMTOT>>>(
        (f16*)p_s, (f16*)p_w1, b1, x, out1, nullptr, Cdim, Cdim);

    // 4) h = rmsnorm(out1) -> fp16
    rmsnorm_h_kernel<<<Mtot, 256>>>(out1, n2w, (f16*)p_h);

    // 5) act = relu(h @ w2a + b2a) -> fp16
    mma_gemm<1><<<dim3(Edim / 128, Mtot / 128), 256, SMTOT>>>(
        (f16*)p_h, (f16*)p_w2a, b2a, nullptr, nullptr, (f16*)p_a, Edim, Cdim);

    // 6) out = act @ w2b + b2b + out1
    mma_gemm<2><<<dim3(Cdim / 128, Mtot / 128), 256, SMTOT>>>(
        (f16*)p_a, (f16*)p_w2b, b2b, out1, out, nullptr, Cdim, Edim);
}